// round 4
// baseline (speedup 1.0000x reference)
#include <cuda_runtime.h>
#include <cuda_bf16.h>

#define NN 50000
#define DD 64
#define EE 800000
#define NEG_INF (-3.402823466e38f)

// ---------------- scratch (static device globals; no allocation) ----------------
__device__ __align__(16) float g_score[NN];
__device__ __align__(16) float g_deg[NN];
__device__ __align__(16) float g_dinv[NN];
__device__ __align__(16) float g_cand_val[49 * 64];
__device__ __align__(16) int   g_cand_idx[49 * 64];
__device__ __align__(16) int   g_perm[64];
__device__ __align__(16) float g_vals[64];
__device__ __align__(16) float g_W[64 * 64];
__device__ __align__(16) float g_xw[(size_t)NN * 64];
__device__ __align__(16) float g_agg[(size_t)NN * 64];
__device__ __align__(16) float g_norm[EE];

// ---------------- 1) score[n] = dot(x[n], p)  (norm applied later; ordering invariant) ----------------
__global__ void score_kernel(const float* __restrict__ x, const float* __restrict__ p) {
    int warp = (blockIdx.x * blockDim.x + threadIdx.x) >> 5;
    int lane = threadIdx.x & 31;
    if (warp >= NN) return;
    float s = x[warp * 64 + lane] * p[lane] + x[warp * 64 + lane + 32] * p[lane + 32];
    #pragma unroll
    for (int off = 16; off > 0; off >>= 1) s += __shfl_down_sync(0xffffffffu, s, off);
    if (lane == 0) { g_score[warp] = s; g_deg[warp] = 1.0f; }  // deg init: self-loop weight
}

// ---------------- 2) top-64: stage 1, per-block top-64 over 1024-chunk ----------------
__global__ void topk1_kernel() {
    __shared__ float sv[1024];
    __shared__ int   si[1024];
    __shared__ float wv[8];
    __shared__ int   wgi[8];
    __shared__ int   wsl[8];
    int tid = threadIdx.x;
    int base = blockIdx.x << 10;
    for (int t = tid; t < 1024; t += 256) {
        int g = base + t;
        sv[t] = (g < NN) ? g_score[g] : NEG_INF;
        si[t] = g;
    }
    __syncthreads();
    for (int k = 0; k < 64; k++) {
        float bv = NEG_INF; int bg = 0x7fffffff, bs = 0;
        #pragma unroll
        for (int j = 0; j < 4; j++) {
            int t = tid + j * 256;
            float v = sv[t]; int g = si[t];
            if (v > bv || (v == bv && g < bg)) { bv = v; bg = g; bs = t; }
        }
        #pragma unroll
        for (int off = 16; off > 0; off >>= 1) {
            float ov = __shfl_down_sync(0xffffffffu, bv, off);
            int   og = __shfl_down_sync(0xffffffffu, bg, off);
            int   os = __shfl_down_sync(0xffffffffu, bs, off);
            if (ov > bv || (ov == bv && og < bg)) { bv = ov; bg = og; bs = os; }
        }
        if ((tid & 31) == 0) { int w = tid >> 5; wv[w] = bv; wgi[w] = bg; wsl[w] = bs; }
        __syncthreads();
        if (tid < 32) {
            bv = (tid < 8) ? wv[tid] : NEG_INF;
            bg = (tid < 8) ? wgi[tid] : 0x7fffffff;
            bs = (tid < 8) ? wsl[tid] : 0;
            #pragma unroll
            for (int off = 4; off > 0; off >>= 1) {
                float ov = __shfl_down_sync(0xffffffffu, bv, off);
                int   og = __shfl_down_sync(0xffffffffu, bg, off);
                int   os = __shfl_down_sync(0xffffffffu, bs, off);
                if (ov > bv || (ov == bv && og < bg)) { bv = ov; bg = og; bs = os; }
            }
            if (tid == 0) {
                g_cand_val[(blockIdx.x << 6) + k] = bv;
                g_cand_idx[(blockIdx.x << 6) + k] = bg;
                sv[bs] = NEG_INF;
            }
        }
        __syncthreads();
    }
}

// ---------------- 2b) top-64: stage 2 over 49*64 = 3136 candidates ----------------
__global__ void topk2_kernel() {
    __shared__ float sv[3136];
    __shared__ int   si[3136];
    __shared__ float wv[32];
    __shared__ int   wgi[32];
    __shared__ int   wsl[32];
    int tid = threadIdx.x;
    for (int t = tid; t < 3136; t += 1024) { sv[t] = g_cand_val[t]; si[t] = g_cand_idx[t]; }
    __syncthreads();
    for (int k = 0; k < 64; k++) {
        float bv = NEG_INF; int bg = 0x7fffffff, bs = 0;
        for (int t = tid; t < 3136; t += 1024) {
            float v = sv[t]; int g = si[t];
            if (v > bv || (v == bv && g < bg)) { bv = v; bg = g; bs = t; }
        }
        #pragma unroll
        for (int off = 16; off > 0; off >>= 1) {
            float ov = __shfl_down_sync(0xffffffffu, bv, off);
            int   og = __shfl_down_sync(0xffffffffu, bg, off);
            int   os = __shfl_down_sync(0xffffffffu, bs, off);
            if (ov > bv || (ov == bv && og < bg)) { bv = ov; bg = og; bs = os; }
        }
        if ((tid & 31) == 0) { int w = tid >> 5; wv[w] = bv; wgi[w] = bg; wsl[w] = bs; }
        __syncthreads();
        if (tid < 32) {
            bv = wv[tid]; bg = wgi[tid]; bs = wsl[tid];
            #pragma unroll
            for (int off = 16; off > 0; off >>= 1) {
                float ov = __shfl_down_sync(0xffffffffu, bv, off);
                int   og = __shfl_down_sync(0xffffffffu, bg, off);
                int   os = __shfl_down_sync(0xffffffffu, bs, off);
                if (ov > bv || (ov == bv && og < bg)) { bv = ov; bg = og; bs = os; }
            }
            if (tid == 0) {
                g_vals[k] = bv;   // raw (unnormalized) score
                g_perm[k] = bg;
                sv[bs] = NEG_INF;
            }
        }
        __syncthreads();
    }
}

// ---------------- 3) x_tilde + GRU step -> evolved weight W [64x64] ----------------
__global__ void gru_kernel(const float* __restrict__ x, const float* __restrict__ p,
                           const float* __restrict__ h0,
                           const float* __restrict__ Wih, const float* __restrict__ Whh,
                           const float* __restrict__ bih, const float* __restrict__ bhh) {
    __shared__ float sxt[64][64];
    __shared__ float sh0[64][64];
    __shared__ float st[64];
    __shared__ float s_pn;
    int tid = threadIdx.x;
    if (tid == 0) {
        float acc = 0.f;
        for (int k = 0; k < 64; k++) acc += p[k] * p[k];
        s_pn = sqrtf(acc);
    }
    __syncthreads();
    if (tid < 64) st[tid] = tanhf(g_vals[tid] / s_pn);
    __syncthreads();
    for (int idx = tid; idx < 4096; idx += 256) {
        int i = idx >> 6, j = idx & 63;
        sxt[i][j] = x[(size_t)g_perm[i] * 64 + j] * st[i];
        sh0[i][j] = h0[idx];
    }
    __syncthreads();
    for (int idx = tid; idx < 4096; idx += 256) {
        int i = idx >> 6, j = idx & 63;
        const float* wr = Wih + j * 64;
        const float* wz = Wih + (64 + j) * 64;
        const float* wn = Wih + (128 + j) * 64;
        const float* vr = Whh + j * 64;
        const float* vz = Whh + (64 + j) * 64;
        const float* vn = Whh + (128 + j) * 64;
        float gir = 0.f, giz = 0.f, gin = 0.f, ghr = 0.f, ghz = 0.f, ghn = 0.f;
        #pragma unroll 8
        for (int k = 0; k < 64; k++) {
            float xt = sxt[i][k], hh = sh0[i][k];
            gir += xt * wr[k]; giz += xt * wz[k]; gin += xt * wn[k];
            ghr += hh * vr[k]; ghz += hh * vz[k]; ghn += hh * vn[k];
        }
        gir += bih[j];       ghr += bhh[j];
        giz += bih[64 + j];  ghz += bhh[64 + j];
        gin += bih[128 + j]; ghn += bhh[128 + j];
        float r  = 1.f / (1.f + expf(-(gir + ghr)));
        float z  = 1.f / (1.f + expf(-(giz + ghz)));
        float nn = tanhf(gin + r * ghn);
        g_W[idx] = (1.f - z) * nn + z * sh0[i][j];
    }
}

// ---------------- 4) degree accumulation over edges (edge_index is INT32) ----------------
__global__ void deg_kernel(const int* __restrict__ ei, const float* __restrict__ w) {
    int e = blockIdx.x * blockDim.x + threadIdx.x;
    if (e < EE) atomicAdd(&g_deg[ei[EE + e]], w[e]);
}

__global__ void dinv_kernel() {
    int n = blockIdx.x * blockDim.x + threadIdx.x;
    if (n < NN) g_dinv[n] = rsqrtf(g_deg[n]);   // deg >= 1 always (self-loop)
}

// ---------------- 5) per-edge norm ----------------
__global__ void norm_kernel(const int* __restrict__ ei, const float* __restrict__ w) {
    int e = blockIdx.x * blockDim.x + threadIdx.x;
    if (e < EE) {
        int r = ei[e];
        int c = ei[EE + e];
        g_norm[e] = g_dinv[r] * w[e] * g_dinv[c];
    }
}

// ---------------- 6) xw = x @ W ----------------
__global__ void xw_kernel(const float* __restrict__ x) {
    __shared__ float sW[64][65];   // padded: stride-64 column reads -> conflict free
    __shared__ float sx[4][64];
    int tid = threadIdx.x;
    for (int idx = tid; idx < 4096; idx += 256) sW[idx >> 6][idx & 63] = g_W[idx];
    int rl = tid >> 6, j = tid & 63;
    int row = blockIdx.x * 4 + rl;
    sx[rl][j] = x[(size_t)row * 64 + j];
    __syncthreads();
    float acc = 0.f;
    #pragma unroll
    for (int k = 0; k < 64; k++) acc += sx[rl][k] * sW[k][j];
    g_xw[(size_t)row * 64 + j] = acc;
}

// ---------------- zero agg ----------------
__global__ void zero_kernel() {
    int i = blockIdx.x * blockDim.x + threadIdx.x;
    if (i < NN * 16) ((float4*)g_agg)[i] = make_float4(0.f, 0.f, 0.f, 0.f);
}

// ---------------- 7) edge scatter: agg[col] += norm * xw[row]
//   16 threads/edge; float4 load + vector float4 atomicAdd (sm_90+ RED) ----------------
__global__ void scatter_kernel(const int* __restrict__ ei) {
    int t = blockIdx.x * 256 + threadIdx.x;     // grid sized exactly: EE*16 threads
    int e = t >> 4, q = t & 15;
    int r = ei[e];
    int c = ei[EE + e];
    float nrm = g_norm[e];
    float4 v = ((const float4*)g_xw)[r * 16 + q];
    atomicAdd(((float4*)g_agg) + c * 16 + q,
              make_float4(nrm * v.x, nrm * v.y, nrm * v.z, nrm * v.w));
}

// ---------------- 8) epilogue: self-loop + relu + Linear(D,1) ----------------
__global__ void out_kernel(const float* __restrict__ linW, const float* __restrict__ linb,
                           float* __restrict__ out) {
    int warp = (blockIdx.x * blockDim.x + threadIdx.x) >> 5;
    int lane = threadIdx.x & 31;
    if (warp >= NN) return;
    float dv = g_dinv[warp];
    float inv = dv * dv;                        // self-loop norm = dinv*1*dinv
    size_t base = (size_t)warp * 64;
    float h0 = g_agg[base + lane]      + g_xw[base + lane]      * inv;
    float h1 = g_agg[base + lane + 32] + g_xw[base + lane + 32] * inv;
    h0 = fmaxf(h0, 0.f);
    h1 = fmaxf(h1, 0.f);
    float acc = h0 * linW[lane] + h1 * linW[lane + 32];
    #pragma unroll
    for (int off = 16; off > 0; off >>= 1) acc += __shfl_down_sync(0xffffffffu, acc, off);
    if (lane == 0) out[warp] = acc + linb[0];
}

// ---------------- launch ----------------
extern "C" void kernel_launch(void* const* d_in, const int* in_sizes, int n_in,
                              void* d_out, int out_size) {
    const float* x      = (const float*)d_in[0];
    const int*   ei     = (const int*)d_in[1];     // int32 (JAX x64 disabled)
    const float* ew     = (const float*)d_in[2];
    const float* pool_p = (const float*)d_in[3];
    const float* init_W = (const float*)d_in[4];
    const float* Wih    = (const float*)d_in[5];
    const float* Whh    = (const float*)d_in[6];
    const float* bih    = (const float*)d_in[7];
    const float* bhh    = (const float*)d_in[8];
    const float* linW   = (const float*)d_in[9];
    const float* linb   = (const float*)d_in[10];
    float* out = (float*)d_out;

    zero_kernel<<<(NN * 16 + 255) / 256, 256>>>();
    score_kernel<<<(NN + 7) / 8, 256>>>(x, pool_p);
    topk1_kernel<<<49, 256>>>();
    topk2_kernel<<<1, 1024>>>();
    gru_kernel<<<1, 256>>>(x, pool_p, init_W, Wih, Whh, bih, bhh);
    deg_kernel<<<(EE + 255) / 256, 256>>>(ei, ew);
    dinv_kernel<<<(NN + 255) / 256, 256>>>();
    norm_kernel<<<(EE + 255) / 256, 256>>>(ei, ew);
    xw_kernel<<<NN / 4, 256>>>(x);
    scatter_kernel<<<EE * 16 / 256, 256>>>(ei);
    out_kernel<<<(NN + 7) / 8, 256>>>(linW, linb, out);
}

// round 6
// speedup vs baseline: 5.9218x; 5.9218x over previous
#include <cuda_runtime.h>
#include <cuda_bf16.h>

#define NN 50000
#define DD 64
#define EE 800000
#define NEG_INF (-3.402823466e38f)

// ---------------- scratch (static device globals; no allocation) ----------------
__device__ __align__(16) float g_score[NN];
__device__ __align__(16) float g_deg[NN];
__device__ __align__(16) float g_dinv[NN];
__device__ __align__(16) float g_cand_val[49 * 64];
__device__ __align__(16) int   g_cand_idx[49 * 64];
__device__ __align__(16) int   g_perm[64];
__device__ __align__(16) float g_vals[64];
__device__ __align__(16) float g_W[64 * 64];
__device__ __align__(16) float g_xw[(size_t)NN * 64];
__device__ __align__(16) float g_agg[(size_t)NN * 64];
__device__ __align__(16) float g_norm[EE];

// ---------------- 1) score[n] = dot(x[n], p)  (norm applied later; ordering invariant) ----------------
__global__ void score_kernel(const float* __restrict__ x, const float* __restrict__ p) {
    int warp = (blockIdx.x * blockDim.x + threadIdx.x) >> 5;
    int lane = threadIdx.x & 31;
    if (warp >= NN) return;
    float s = x[warp * 64 + lane] * p[lane] + x[warp * 64 + lane + 32] * p[lane + 32];
    #pragma unroll
    for (int off = 16; off > 0; off >>= 1) s += __shfl_down_sync(0xffffffffu, s, off);
    if (lane == 0) { g_score[warp] = s; g_deg[warp] = 1.0f; }  // deg init: self-loop weight
}

// ---------------- 2) top-64: stage 1, per-block top-64 over 1024-chunk ----------------
__global__ void topk1_kernel() {
    __shared__ float sv[1024];
    __shared__ int   si[1024];
    __shared__ float wv[8];
    __shared__ int   wgi[8];
    __shared__ int   wsl[8];
    int tid = threadIdx.x;
    int base = blockIdx.x << 10;
    for (int t = tid; t < 1024; t += 256) {
        int g = base + t;
        sv[t] = (g < NN) ? g_score[g] : NEG_INF;
        si[t] = g;
    }
    __syncthreads();
    for (int k = 0; k < 64; k++) {
        float bv = NEG_INF; int bg = 0x7fffffff, bs = 0;
        #pragma unroll
        for (int j = 0; j < 4; j++) {
            int t = tid + j * 256;
            float v = sv[t]; int g = si[t];
            if (v > bv || (v == bv && g < bg)) { bv = v; bg = g; bs = t; }
        }
        #pragma unroll
        for (int off = 16; off > 0; off >>= 1) {
            float ov = __shfl_down_sync(0xffffffffu, bv, off);
            int   og = __shfl_down_sync(0xffffffffu, bg, off);
            int   os = __shfl_down_sync(0xffffffffu, bs, off);
            if (ov > bv || (ov == bv && og < bg)) { bv = ov; bg = og; bs = os; }
        }
        if ((tid & 31) == 0) { int w = tid >> 5; wv[w] = bv; wgi[w] = bg; wsl[w] = bs; }
        __syncthreads();
        if (tid < 32) {
            bv = (tid < 8) ? wv[tid] : NEG_INF;
            bg = (tid < 8) ? wgi[tid] : 0x7fffffff;
            bs = (tid < 8) ? wsl[tid] : 0;
            #pragma unroll
            for (int off = 4; off > 0; off >>= 1) {
                float ov = __shfl_down_sync(0xffffffffu, bv, off);
                int   og = __shfl_down_sync(0xffffffffu, bg, off);
                int   os = __shfl_down_sync(0xffffffffu, bs, off);
                if (ov > bv || (ov == bv && og < bg)) { bv = ov; bg = og; bs = os; }
            }
            if (tid == 0) {
                g_cand_val[(blockIdx.x << 6) + k] = bv;
                g_cand_idx[(blockIdx.x << 6) + k] = bg;
                sv[bs] = NEG_INF;
            }
        }
        __syncthreads();
    }
}

// ---------------- 2b) top-64: stage 2 over 49*64 = 3136 candidates ----------------
__global__ void topk2_kernel() {
    __shared__ float sv[3136];
    __shared__ int   si[3136];
    __shared__ float wv[32];
    __shared__ int   wgi[32];
    __shared__ int   wsl[32];
    int tid = threadIdx.x;
    for (int t = tid; t < 3136; t += 1024) { sv[t] = g_cand_val[t]; si[t] = g_cand_idx[t]; }
    __syncthreads();
    for (int k = 0; k < 64; k++) {
        float bv = NEG_INF; int bg = 0x7fffffff, bs = 0;
        for (int t = tid; t < 3136; t += 1024) {
            float v = sv[t]; int g = si[t];
            if (v > bv || (v == bv && g < bg)) { bv = v; bg = g; bs = t; }
        }
        #pragma unroll
        for (int off = 16; off > 0; off >>= 1) {
            float ov = __shfl_down_sync(0xffffffffu, bv, off);
            int   og = __shfl_down_sync(0xffffffffu, bg, off);
            int   os = __shfl_down_sync(0xffffffffu, bs, off);
            if (ov > bv || (ov == bv && og < bg)) { bv = ov; bg = og; bs = os; }
        }
        if ((tid & 31) == 0) { int w = tid >> 5; wv[w] = bv; wgi[w] = bg; wsl[w] = bs; }
        __syncthreads();
        if (tid < 32) {
            bv = wv[tid]; bg = wgi[tid]; bs = wsl[tid];
            #pragma unroll
            for (int off = 16; off > 0; off >>= 1) {
                float ov = __shfl_down_sync(0xffffffffu, bv, off);
                int   og = __shfl_down_sync(0xffffffffu, bg, off);
                int   os = __shfl_down_sync(0xffffffffu, bs, off);
                if (ov > bv || (ov == bv && og < bg)) { bv = ov; bg = og; bs = os; }
            }
            if (tid == 0) {
                g_vals[k] = bv;   // raw (unnormalized) score
                g_perm[k] = bg;
                sv[bs] = NEG_INF;
            }
        }
        __syncthreads();
    }
}

// ---------------- 3) GRU step -> evolved weight W [64x64]
//   64 blocks (one per output column j) x 64 threads (one per row i).
//   All weight loads coalesced into smem; inner loop is pure smem FMA. ----------------
__global__ void gru_kernel(const float* __restrict__ x, const float* __restrict__ p,
                           const float* __restrict__ h0,
                           const float* __restrict__ Wih, const float* __restrict__ Whh,
                           const float* __restrict__ bih, const float* __restrict__ bhh) {
    __shared__ float sxt[64][65];   // x_tilde, padded (stride 65 -> conflict-free)
    __shared__ float sh0[64][65];
    __shared__ float wr[64], wz[64], wn[64], vr[64], vz[64], vn[64];
    __shared__ float st[64];
    __shared__ float s_part[2];
    __shared__ float s_rpn;
    int t = threadIdx.x;            // 0..63
    int j = blockIdx.x;             // 0..63

    // ||p|| reduction over 64 values (2 warps)
    float pv = p[t];
    float sq = pv * pv;
    #pragma unroll
    for (int off = 16; off > 0; off >>= 1) sq += __shfl_down_sync(0xffffffffu, sq, off);
    if ((t & 31) == 0) s_part[t >> 5] = sq;
    __syncthreads();
    if (t == 0) s_rpn = rsqrtf(s_part[0] + s_part[1]);
    __syncthreads();
    st[t] = tanhf(g_vals[t] * s_rpn);

    // coalesced weight-row loads (rows j, 64+j, 128+j)
    wr[t] = Wih[j * 64 + t];
    wz[t] = Wih[(64 + j) * 64 + t];
    wn[t] = Wih[(128 + j) * 64 + t];
    vr[t] = Whh[j * 64 + t];
    vz[t] = Whh[(64 + j) * 64 + t];
    vn[t] = Whh[(128 + j) * 64 + t];
    __syncthreads();                // st ready before use below

    for (int i = 0; i < 64; i++) {
        sxt[i][t] = x[(size_t)g_perm[i] * 64 + t] * st[i];
        sh0[i][t] = h0[i * 64 + t];
    }
    __syncthreads();

    int i = t;
    float gir = bih[j], giz = bih[64 + j], gin = bih[128 + j];
    float ghr = bhh[j], ghz = bhh[64 + j], ghn = bhh[128 + j];
    #pragma unroll 8
    for (int k = 0; k < 64; k++) {
        float xt = sxt[i][k], hh = sh0[i][k];
        gir += xt * wr[k]; giz += xt * wz[k]; gin += xt * wn[k];
        ghr += hh * vr[k]; ghz += hh * vz[k]; ghn += hh * vn[k];
    }
    float r   = 1.f / (1.f + expf(-(gir + ghr)));
    float z   = 1.f / (1.f + expf(-(giz + ghz)));
    float nnv = tanhf(gin + r * ghn);
    g_W[i * 64 + j] = (1.f - z) * nnv + z * sh0[i][j];
}

// ---------------- 4) degree accumulation over edges (edge_index is INT32) ----------------
__global__ void deg_kernel(const int* __restrict__ ei, const float* __restrict__ w) {
    int e = blockIdx.x * blockDim.x + threadIdx.x;
    if (e < EE) atomicAdd(&g_deg[ei[EE + e]], w[e]);
}

__global__ void dinv_kernel() {
    int n = blockIdx.x * blockDim.x + threadIdx.x;
    if (n < NN) g_dinv[n] = rsqrtf(g_deg[n]);   // deg >= 1 always (self-loop)
}

// ---------------- 5) per-edge norm ----------------
__global__ void norm_kernel(const int* __restrict__ ei, const float* __restrict__ w) {
    int e = blockIdx.x * blockDim.x + threadIdx.x;
    if (e < EE) {
        int r = ei[e];
        int c = ei[EE + e];
        g_norm[e] = g_dinv[r] * w[e] * g_dinv[c];
    }
}

// ---------------- 6) xw = x @ W ----------------
__global__ void xw_kernel(const float* __restrict__ x) {
    __shared__ float sW[64][65];   // padded: stride-64 column reads -> conflict free
    __shared__ float sx[4][64];
    int tid = threadIdx.x;
    for (int idx = tid; idx < 4096; idx += 256) sW[idx >> 6][idx & 63] = g_W[idx];
    int rl = tid >> 6, j = tid & 63;
    int row = blockIdx.x * 4 + rl;
    sx[rl][j] = x[(size_t)row * 64 + j];
    __syncthreads();
    float acc = 0.f;
    #pragma unroll
    for (int k = 0; k < 64; k++) acc += sx[rl][k] * sW[k][j];
    g_xw[(size_t)row * 64 + j] = acc;
}

// ---------------- zero agg ----------------
__global__ void zero_kernel() {
    int i = blockIdx.x * blockDim.x + threadIdx.x;
    if (i < NN * 16) ((float4*)g_agg)[i] = make_float4(0.f, 0.f, 0.f, 0.f);
}

// ---------------- 7) edge scatter: agg[col] += norm * xw[row]
//   16 threads/edge; float4 load + vector float4 atomicAdd (sm_90+ RED) ----------------
__global__ void scatter_kernel(const int* __restrict__ ei) {
    int t = blockIdx.x * 256 + threadIdx.x;     // grid sized exactly: EE*16 threads
    int e = t >> 4, q = t & 15;
    int r = ei[e];
    int c = ei[EE + e];
    float nrm = g_norm[e];
    float4 v = ((const float4*)g_xw)[r * 16 + q];
    atomicAdd(((float4*)g_agg) + c * 16 + q,
              make_float4(nrm * v.x, nrm * v.y, nrm * v.z, nrm * v.w));
}

// ---------------- 8) epilogue: self-loop + relu + Linear(D,1) ----------------
__global__ void out_kernel(const float* __restrict__ linW, const float* __restrict__ linb,
                           float* __restrict__ out) {
    int warp = (blockIdx.x * blockDim.x + threadIdx.x) >> 5;
    int lane = threadIdx.x & 31;
    if (warp >= NN) return;
    float dv = g_dinv[warp];
    float inv = dv * dv;                        // self-loop norm = dinv*1*dinv
    size_t base = (size_t)warp * 64;
    float h0 = g_agg[base + lane]      + g_xw[base + lane]      * inv;
    float h1 = g_agg[base + lane + 32] + g_xw[base + lane + 32] * inv;
    h0 = fmaxf(h0, 0.f);
    h1 = fmaxf(h1, 0.f);
    float acc = h0 * linW[lane] + h1 * linW[lane + 32];
    #pragma unroll
    for (int off = 16; off > 0; off >>= 1) acc += __shfl_down_sync(0xffffffffu, acc, off);
    if (lane == 0) out[warp] = acc + linb[0];
}

// ---------------- launch ----------------
extern "C" void kernel_launch(void* const* d_in, const int* in_sizes, int n_in,
                              void* d_out, int out_size) {
    const float* x      = (const float*)d_in[0];
    const int*   ei     = (const int*)d_in[1];     // int32 (JAX x64 disabled)
    const float* ew     = (const float*)d_in[2];
    const float* pool_p = (const float*)d_in[3];
    const float* init_W = (const float*)d_in[4];
    const float* Wih    = (const float*)d_in[5];
    const float* Whh    = (const float*)d_in[6];
    const float* bih    = (const float*)d_in[7];
    const float* bhh    = (const float*)d_in[8];
    const float* linW   = (const float*)d_in[9];
    const float* linb   = (const float*)d_in[10];
    float* out = (float*)d_out;

    zero_kernel<<<(NN * 16 + 255) / 256, 256>>>();
    score_kernel<<<(NN + 7) / 8, 256>>>(x, pool_p);
    topk1_kernel<<<49, 256>>>();
    topk2_kernel<<<1, 1024>>>();
    gru_kernel<<<64, 64>>>(x, pool_p, init_W, Wih, Whh, bih, bhh);
    deg_kernel<<<(EE + 255) / 256, 256>>>(ei, ew);
    dinv_kernel<<<(NN + 255) / 256, 256>>>();
    norm_kernel<<<(EE + 255) / 256, 256>>>(ei, ew);
    xw_kernel<<<NN / 4, 256>>>(x);
    scatter_kernel<<<EE * 16 / 256, 256>>>(ei);
    out_kernel<<<(NN + 7) / 8, 256>>>(linW, linb, out);
}

// round 7
// speedup vs baseline: 8.5298x; 1.4404x over previous
#include <cuda_runtime.h>
#include <cuda_bf16.h>

#define NN 50000
#define DD 64
#define EE 800000
#define CAP 4096
#define NEG_INF (-3.402823466e38f)

// ---------------- scratch (static device globals; no allocation) ----------------
__device__ __align__(16) float g_score[NN];
__device__ __align__(16) float g_deg[NN];
__device__ __align__(16) unsigned int g_hist[4096];
__device__ unsigned int g_thresh_key;
__device__ int g_ccount;
__device__ __align__(16) float g_cand_val[CAP];
__device__ __align__(16) int   g_cand_idx[CAP];
__device__ __align__(16) int   g_perm[64];
__device__ __align__(16) float g_vals[64];
__device__ __align__(16) float g_W[64 * 64];
__device__ __align__(16) float g_xw[(size_t)NN * 64];
__device__ __align__(16) float g_agg[(size_t)NN * 64];

__device__ __forceinline__ unsigned int key_of(float f) {
    unsigned int u = __float_as_uint(f);
    return u ^ ((u >> 31) ? 0xFFFFFFFFu : 0x80000000u);   // monotone: float order -> uint order
}

// ---------------- 0) zero agg / hist / counter ----------------
__global__ void zero_kernel() {
    int i = blockIdx.x * blockDim.x + threadIdx.x;
    if (i < NN * 16) ((float4*)g_agg)[i] = make_float4(0.f, 0.f, 0.f, 0.f);
    if (i < 4096) g_hist[i] = 0u;
    if (i == 0) g_ccount = 0;
}

// ---------------- 1) score[n] = dot(x[n], p); histogram of keys; deg init ----------------
__global__ void score_kernel(const float* __restrict__ x, const float* __restrict__ p) {
    int warp = (blockIdx.x * blockDim.x + threadIdx.x) >> 5;
    int lane = threadIdx.x & 31;
    if (warp >= NN) return;
    float s = x[warp * 64 + lane] * p[lane] + x[warp * 64 + lane + 32] * p[lane + 32];
    #pragma unroll
    for (int off = 16; off > 0; off >>= 1) s += __shfl_down_sync(0xffffffffu, s, off);
    if (lane == 0) {
        g_score[warp] = s;
        g_deg[warp] = 1.0f;                       // self-loop weight
        atomicAdd(&g_hist[key_of(s) >> 20], 1u);  // 4096 bins
    }
}

// ---------------- 2) find threshold bin: 64th-largest key's bin lower bound ----------------
__global__ void thresh_kernel() {
    __shared__ int chunk[256];
    __shared__ int incl[256];
    int t = threadIdx.x;
    // chunk t = sum of 16 bins counting DOWN from the top
    int s = 0;
    #pragma unroll
    for (int i = 0; i < 16; i++) s += (int)g_hist[4095 - 16 * t - i];
    chunk[t] = s;
    __syncthreads();
    // inclusive Hillis-Steele scan over chunks (top-down order)
    int v = s;
    for (int off = 1; off < 256; off <<= 1) {
        incl[t] = v; __syncthreads();
        if (t >= off) v += incl[t - off];
        __syncthreads();
    }
    incl[t] = v; __syncthreads();
    int excl = v - chunk[t];
    if (excl < 64 && v >= 64) {          // crossing chunk: walk its 16 bins from top
        int acc = excl;
        for (int i = 0; i < 16; i++) {
            int b = 4095 - 16 * t - i;
            acc += (int)g_hist[b];
            if (acc >= 64) { g_thresh_key = ((unsigned int)b) << 20; break; }
        }
    }
}

// ---------------- 3) compact candidates with key >= threshold ----------------
__global__ void collect_kernel() {
    int n = blockIdx.x * blockDim.x + threadIdx.x;
    if (n >= NN) return;
    float s = g_score[n];
    if (key_of(s) >= g_thresh_key) {
        int pos = atomicAdd(&g_ccount, 1);
        if (pos < CAP) { g_cand_val[pos] = s; g_cand_idx[pos] = n; }
    }
}

// ---------------- 4) exact top-64 over ~100 candidates (single warp, no barriers) ----------------
__global__ void final_topk_kernel() {
    __shared__ float sv[CAP];
    __shared__ int   si[CAP];
    int lane = threadIdx.x;
    int M = g_ccount; if (M > CAP) M = CAP;
    for (int t = lane; t < M; t += 32) { sv[t] = g_cand_val[t]; si[t] = g_cand_idx[t]; }
    __syncwarp();
    for (int k = 0; k < 64; k++) {
        float bv = NEG_INF; int bg = 0x7fffffff, bs = 0;
        for (int t = lane; t < M; t += 32) {
            float v = sv[t]; int g = si[t];
            if (v > bv || (v == bv && g < bg)) { bv = v; bg = g; bs = t; }
        }
        #pragma unroll
        for (int off = 16; off > 0; off >>= 1) {
            float ov = __shfl_down_sync(0xffffffffu, bv, off);
            int   og = __shfl_down_sync(0xffffffffu, bg, off);
            int   os = __shfl_down_sync(0xffffffffu, bs, off);
            if (ov > bv || (ov == bv && og < bg)) { bv = ov; bg = og; bs = os; }
        }
        if (lane == 0) {
            g_vals[k] = bv;
            g_perm[k] = bg;
            sv[bs] = NEG_INF;
        }
        __syncwarp();
    }
}

// ---------------- 5) GRU step -> evolved weight W [64x64]
//   64 blocks (one per output column j) x 64 threads (one per row i). ----------------
__global__ void gru_kernel(const float* __restrict__ x, const float* __restrict__ p,
                           const float* __restrict__ h0,
                           const float* __restrict__ Wih, const float* __restrict__ Whh,
                           const float* __restrict__ bih, const float* __restrict__ bhh) {
    __shared__ float sxt[64][65];
    __shared__ float sh0[64][65];
    __shared__ float wr[64], wz[64], wn[64], vr[64], vz[64], vn[64];
    __shared__ float st[64];
    __shared__ float s_part[2];
    __shared__ float s_rpn;
    int t = threadIdx.x;            // 0..63
    int j = blockIdx.x;             // 0..63

    float pv = p[t];
    float sq = pv * pv;
    #pragma unroll
    for (int off = 16; off > 0; off >>= 1) sq += __shfl_down_sync(0xffffffffu, sq, off);
    if ((t & 31) == 0) s_part[t >> 5] = sq;
    __syncthreads();
    if (t == 0) s_rpn = rsqrtf(s_part[0] + s_part[1]);
    __syncthreads();
    st[t] = tanhf(g_vals[t] * s_rpn);

    wr[t] = Wih[j * 64 + t];
    wz[t] = Wih[(64 + j) * 64 + t];
    wn[t] = Wih[(128 + j) * 64 + t];
    vr[t] = Whh[j * 64 + t];
    vz[t] = Whh[(64 + j) * 64 + t];
    vn[t] = Whh[(128 + j) * 64 + t];
    __syncthreads();

    for (int i = 0; i < 64; i++) {
        sxt[i][t] = x[(size_t)g_perm[i] * 64 + t] * st[i];
        sh0[i][t] = h0[i * 64 + t];
    }
    __syncthreads();

    int i = t;
    float gir = bih[j], giz = bih[64 + j], gin = bih[128 + j];
    float ghr = bhh[j], ghz = bhh[64 + j], ghn = bhh[128 + j];
    #pragma unroll 8
    for (int k = 0; k < 64; k++) {
        float xt = sxt[i][k], hh = sh0[i][k];
        gir += xt * wr[k]; giz += xt * wz[k]; gin += xt * wn[k];
        ghr += hh * vr[k]; ghz += hh * vz[k]; ghn += hh * vn[k];
    }
    float r   = 1.f / (1.f + expf(-(gir + ghr)));
    float z   = 1.f / (1.f + expf(-(giz + ghz)));
    float nnv = tanhf(gin + r * ghn);
    g_W[i * 64 + j] = (1.f - z) * nnv + z * sh0[i][j];
}

// ---------------- 6) degree accumulation over edges (edge_index is INT32) ----------------
__global__ void deg_kernel(const int* __restrict__ ei, const float* __restrict__ w) {
    int e = blockIdx.x * blockDim.x + threadIdx.x;
    if (e < EE) atomicAdd(&g_deg[ei[EE + e]], w[e]);
}

// ---------------- 7) xw = x @ W  (16 rows/block, 4 outputs/thread, float4) ----------------
__global__ void xw_kernel(const float* __restrict__ x) {
    __shared__ float sW[64][64];
    __shared__ float sx[16][64];
    int tid = threadIdx.x;
    for (int i = tid; i < 1024; i += 256) ((float4*)sW)[i] = ((const float4*)g_W)[i];
    int row0 = blockIdx.x * 16;
    for (int i = tid; i < 256; i += 256)
        ((float4*)sx)[i] = ((const float4*)(x + (size_t)row0 * 64))[i];
    __syncthreads();
    int r = tid >> 4, c4 = tid & 15;
    float4 acc = make_float4(0.f, 0.f, 0.f, 0.f);
    #pragma unroll 16
    for (int k = 0; k < 64; k++) {
        float xv = sx[r][k];
        float4 w4 = *(const float4*)&sW[k][c4 * 4];
        acc.x += xv * w4.x; acc.y += xv * w4.y; acc.z += xv * w4.z; acc.w += xv * w4.w;
    }
    ((float4*)g_xw)[(size_t)(row0 + r) * 16 + c4] = acc;
}

// ---------------- 8) edge scatter: agg[col] += norm * xw[row]
//   16 threads/edge; leader computes norm inline (no norm pass), shfl broadcast;
//   float4 load + vector float4 atomicAdd (sm_90+ RED) ----------------
__global__ void scatter_kernel(const int* __restrict__ ei, const float* __restrict__ ew) {
    int t = blockIdx.x * 256 + threadIdx.x;     // grid sized exactly: EE*16 threads
    int e = t >> 4, q = t & 15;
    int r = ei[e];
    int c = ei[EE + e];
    float nrm = 0.f;
    if (q == 0) nrm = rsqrtf(g_deg[r]) * ew[e] * rsqrtf(g_deg[c]);
    nrm = __shfl_sync(0xffffffffu, nrm, threadIdx.x & 16);   // broadcast from sub-group leader
    float4 v = ((const float4*)g_xw)[r * 16 + q];
    atomicAdd(((float4*)g_agg) + c * 16 + q,
              make_float4(nrm * v.x, nrm * v.y, nrm * v.z, nrm * v.w));
}

// ---------------- 9) epilogue: self-loop + relu + Linear(D,1) ----------------
__global__ void out_kernel(const float* __restrict__ linW, const float* __restrict__ linb,
                           float* __restrict__ out) {
    int warp = (blockIdx.x * blockDim.x + threadIdx.x) >> 5;
    int lane = threadIdx.x & 31;
    if (warp >= NN) return;
    float dv = rsqrtf(g_deg[warp]);
    float inv = dv * dv;                        // self-loop norm = dinv*1*dinv
    size_t base = (size_t)warp * 64;
    float h0 = g_agg[base + lane]      + g_xw[base + lane]      * inv;
    float h1 = g_agg[base + lane + 32] + g_xw[base + lane + 32] * inv;
    h0 = fmaxf(h0, 0.f);
    h1 = fmaxf(h1, 0.f);
    float acc = h0 * linW[lane] + h1 * linW[lane + 32];
    #pragma unroll
    for (int off = 16; off > 0; off >>= 1) acc += __shfl_down_sync(0xffffffffu, acc, off);
    if (lane == 0) out[warp] = acc + linb[0];
}

// ---------------- launch ----------------
extern "C" void kernel_launch(void* const* d_in, const int* in_sizes, int n_in,
                              void* d_out, int out_size) {
    const float* x      = (const float*)d_in[0];
    const int*   ei     = (const int*)d_in[1];     // int32 (JAX x64 disabled)
    const float* ew     = (const float*)d_in[2];
    const float* pool_p = (const float*)d_in[3];
    const float* init_W = (const float*)d_in[4];
    const float* Wih    = (const float*)d_in[5];
    const float* Whh    = (const float*)d_in[6];
    const float* bih    = (const float*)d_in[7];
    const float* bhh    = (const float*)d_in[8];
    const float* linW   = (const float*)d_in[9];
    const float* linb   = (const float*)d_in[10];
    float* out = (float*)d_out;

    zero_kernel<<<(NN * 16 + 255) / 256, 256>>>();
    score_kernel<<<(NN + 7) / 8, 256>>>(x, pool_p);
    deg_kernel<<<(EE + 255) / 256, 256>>>(ei, ew);
    thresh_kernel<<<1, 256>>>();
    collect_kernel<<<(NN + 255) / 256, 256>>>();
    final_topk_kernel<<<1, 32>>>();
    gru_kernel<<<64, 64>>>(x, pool_p, init_W, Wih, Whh, bih, bhh);
    xw_kernel<<<(NN + 15) / 16, 256>>>(x);
    scatter_kernel<<<EE * 16 / 256, 256>>>(ei, ew);
    out_kernel<<<(NN + 7) / 8, 256>>>(linW, linb, out);
}

// round 8
// speedup vs baseline: 8.6493x; 1.0140x over previous
#include <cuda_runtime.h>
#include <cuda_bf16.h>

#define NN 50000
#define DD 64
#define EE 800000
#define CAP 4096
#define NEG_INF (-3.402823466e38f)
#define SCAN_B 512
#define SCAN_NB ((NN + SCAN_B - 1) / SCAN_B)   // 98

// ---------------- scratch (static device globals; no allocation) ----------------
__device__ __align__(16) float g_score[NN];
__device__ __align__(16) float g_deg[NN];
__device__ __align__(16) int   g_cnt[NN];
__device__ __align__(16) int   g_off[NN];
__device__ __align__(16) int   g_cur[NN];
__device__ __align__(16) int   g_bsum[SCAN_NB];
__device__ __align__(16) int   g_boff[SCAN_NB];
__device__ __align__(16) int   g_src[EE];
__device__ __align__(16) float g_wv[EE];
__device__ __align__(16) unsigned int g_hist[4096];
__device__ unsigned int g_thresh_key;
__device__ int g_ccount;
__device__ __align__(16) float g_cand_val[CAP];
__device__ __align__(16) int   g_cand_idx[CAP];
__device__ __align__(16) int   g_perm[64];
__device__ __align__(16) float g_vals[64];
__device__ __align__(16) float g_W[64 * 64];
__device__ __align__(16) float g_xw[(size_t)NN * 64];

__device__ __forceinline__ unsigned int key_of(float f) {
    unsigned int u = __float_as_uint(f);
    return u ^ ((u >> 31) ? 0xFFFFFFFFu : 0x80000000u);   // monotone: float order -> uint order
}

// ---------------- 0) zero cnt/cur/deg/hist/counter ----------------
__global__ void zero_kernel() {
    int i = blockIdx.x * blockDim.x + threadIdx.x;
    if (i < NN) { g_cnt[i] = 0; g_cur[i] = 0; g_deg[i] = 1.0f; }   // deg init: self-loop
    if (i < 4096) g_hist[i] = 0u;
    if (i == 0) g_ccount = 0;
}

// ---------------- 1) score[n] = dot(x[n], p); histogram of keys ----------------
__global__ void score_kernel(const float* __restrict__ x, const float* __restrict__ p) {
    int warp = (blockIdx.x * blockDim.x + threadIdx.x) >> 5;
    int lane = threadIdx.x & 31;
    if (warp >= NN) return;
    float s = x[warp * 64 + lane] * p[lane] + x[warp * 64 + lane + 32] * p[lane + 32];
    #pragma unroll
    for (int off = 16; off > 0; off >>= 1) s += __shfl_down_sync(0xffffffffu, s, off);
    if (lane == 0) {
        g_score[warp] = s;
        atomicAdd(&g_hist[key_of(s) >> 20], 1u);  // 4096 bins
    }
}

// ---------------- 2) find threshold bin: 64th-largest key's bin lower bound ----------------
__global__ void thresh_kernel() {
    __shared__ int chunk[256];
    __shared__ int incl[256];
    int t = threadIdx.x;
    int s = 0;
    #pragma unroll
    for (int i = 0; i < 16; i++) s += (int)g_hist[4095 - 16 * t - i];
    chunk[t] = s;
    __syncthreads();
    int v = s;
    for (int off = 1; off < 256; off <<= 1) {
        incl[t] = v; __syncthreads();
        if (t >= off) v += incl[t - off];
        __syncthreads();
    }
    incl[t] = v; __syncthreads();
    int excl = v - chunk[t];
    if (excl < 64 && v >= 64) {          // crossing chunk: walk its 16 bins from top
        int acc = excl;
        for (int i = 0; i < 16; i++) {
            int b = 4095 - 16 * t - i;
            acc += (int)g_hist[b];
            if (acc >= 64) { g_thresh_key = ((unsigned int)b) << 20; break; }
        }
    }
}

// ---------------- 3) compact candidates with key >= threshold ----------------
__global__ void collect_kernel() {
    int n = blockIdx.x * blockDim.x + threadIdx.x;
    if (n >= NN) return;
    float s = g_score[n];
    if (key_of(s) >= g_thresh_key) {
        int pos = atomicAdd(&g_ccount, 1);
        if (pos < CAP) { g_cand_val[pos] = s; g_cand_idx[pos] = n; }
    }
}

// ---------------- 4) exact top-64 over ~100 candidates (single warp) ----------------
__global__ void final_topk_kernel() {
    __shared__ float sv[CAP];
    __shared__ int   si[CAP];
    int lane = threadIdx.x;
    int M = g_ccount; if (M > CAP) M = CAP;
    for (int t = lane; t < M; t += 32) { sv[t] = g_cand_val[t]; si[t] = g_cand_idx[t]; }
    __syncwarp();
    for (int k = 0; k < 64; k++) {
        float bv = NEG_INF; int bg = 0x7fffffff, bs = 0;
        for (int t = lane; t < M; t += 32) {
            float v = sv[t]; int g = si[t];
            if (v > bv || (v == bv && g < bg)) { bv = v; bg = g; bs = t; }
        }
        #pragma unroll
        for (int off = 16; off > 0; off >>= 1) {
            float ov = __shfl_down_sync(0xffffffffu, bv, off);
            int   og = __shfl_down_sync(0xffffffffu, bg, off);
            int   os = __shfl_down_sync(0xffffffffu, bs, off);
            if (ov > bv || (ov == bv && og < bg)) { bv = ov; bg = og; bs = os; }
        }
        if (lane == 0) {
            g_vals[k] = bv;
            g_perm[k] = bg;
            sv[bs] = NEG_INF;
        }
        __syncwarp();
    }
}

// ---------------- 5) GRU step -> evolved weight W [64x64] ----------------
__global__ void gru_kernel(const float* __restrict__ x, const float* __restrict__ p,
                           const float* __restrict__ h0,
                           const float* __restrict__ Wih, const float* __restrict__ Whh,
                           const float* __restrict__ bih, const float* __restrict__ bhh) {
    __shared__ float sxt[64][65];
    __shared__ float sh0[64][65];
    __shared__ float wr[64], wz[64], wn[64], vr[64], vz[64], vn[64];
    __shared__ float st[64];
    __shared__ float s_part[2];
    __shared__ float s_rpn;
    int t = threadIdx.x;            // 0..63
    int j = blockIdx.x;             // 0..63

    float pv = p[t];
    float sq = pv * pv;
    #pragma unroll
    for (int off = 16; off > 0; off >>= 1) sq += __shfl_down_sync(0xffffffffu, sq, off);
    if ((t & 31) == 0) s_part[t >> 5] = sq;
    __syncthreads();
    if (t == 0) s_rpn = rsqrtf(s_part[0] + s_part[1]);
    __syncthreads();
    st[t] = tanhf(g_vals[t] * s_rpn);

    wr[t] = Wih[j * 64 + t];
    wz[t] = Wih[(64 + j) * 64 + t];
    wn[t] = Wih[(128 + j) * 64 + t];
    vr[t] = Whh[j * 64 + t];
    vz[t] = Whh[(64 + j) * 64 + t];
    vn[t] = Whh[(128 + j) * 64 + t];
    __syncthreads();

    for (int i = 0; i < 64; i++) {
        sxt[i][t] = x[(size_t)g_perm[i] * 64 + t] * st[i];
        sh0[i][t] = h0[i * 64 + t];
    }
    __syncthreads();

    int i = t;
    float gir = bih[j], giz = bih[64 + j], gin = bih[128 + j];
    float ghr = bhh[j], ghz = bhh[64 + j], ghn = bhh[128 + j];
    #pragma unroll 8
    for (int k = 0; k < 64; k++) {
        float xt = sxt[i][k], hh = sh0[i][k];
        gir += xt * wr[k]; giz += xt * wz[k]; gin += xt * wn[k];
        ghr += hh * vr[k]; ghz += hh * vz[k]; ghn += hh * vn[k];
    }
    float r   = 1.f / (1.f + expf(-(gir + ghr)));
    float z   = 1.f / (1.f + expf(-(giz + ghz)));
    float nnv = tanhf(gin + r * ghn);
    g_W[i * 64 + j] = (1.f - z) * nnv + z * sh0[i][j];
}

// ---------------- 6) per-target degree (float) + in-degree count (int) ----------------
__global__ void count_kernel(const int* __restrict__ ei, const float* __restrict__ w) {
    int e = blockIdx.x * blockDim.x + threadIdx.x;
    if (e < EE) {
        int c = ei[EE + e];
        atomicAdd(&g_deg[c], w[e]);
        atomicAdd(&g_cnt[c], 1);
    }
}

// ---------------- 7) exclusive scan of g_cnt -> g_off (3 steps) ----------------
__global__ void scan_part_kernel() {
    __shared__ int sh[SCAN_B];
    int t = threadIdx.x;
    int n = blockIdx.x * SCAN_B + t;
    int v = (n < NN) ? g_cnt[n] : 0;
    sh[t] = v;
    __syncthreads();
    int acc = v;
    for (int off = 1; off < SCAN_B; off <<= 1) {
        int add = (t >= off) ? sh[t - off] : 0;
        __syncthreads();
        acc += add; sh[t] = acc;
        __syncthreads();
    }
    if (n < NN) g_off[n] = acc - v;            // local exclusive
    if (t == SCAN_B - 1) g_bsum[blockIdx.x] = acc;
}

__global__ void scan_top_kernel() {
    __shared__ int sh[128];
    int t = threadIdx.x;
    int v = (t < SCAN_NB) ? g_bsum[t] : 0;
    sh[t] = v;
    __syncthreads();
    int acc = v;
    for (int off = 1; off < 128; off <<= 1) {
        int add = (t >= off) ? sh[t - off] : 0;
        __syncthreads();
        acc += add; sh[t] = acc;
        __syncthreads();
    }
    if (t < SCAN_NB) g_boff[t] = acc - v;      // exclusive over block sums
}

__global__ void scan_add_kernel() {
    int n = blockIdx.x * SCAN_B + threadIdx.x;
    if (n < NN) g_off[n] += g_boff[blockIdx.x];
}

// ---------------- 8) fill CSR: slot (src, norm) into target's segment ----------------
__global__ void fill_kernel(const int* __restrict__ ei, const float* __restrict__ w) {
    int e = blockIdx.x * blockDim.x + threadIdx.x;
    if (e >= EE) return;
    int r = ei[e];
    int c = ei[EE + e];
    float nrm = rsqrtf(g_deg[r]) * w[e] * rsqrtf(g_deg[c]);
    int pos = g_off[c] + atomicAdd(&g_cur[c], 1);
    g_src[pos] = r;
    g_wv[pos] = nrm;
}

// ---------------- 9) xw = x @ W  (16 rows/block, 4 outputs/thread, float4) ----------------
__global__ void xw_kernel(const float* __restrict__ x) {
    __shared__ float sW[64][64];
    __shared__ float sx[16][64];
    int tid = threadIdx.x;
    for (int i = tid; i < 1024; i += 256) ((float4*)sW)[i] = ((const float4*)g_W)[i];
    int row0 = blockIdx.x * 16;
    for (int i = tid; i < 256; i += 256)
        ((float4*)sx)[i] = ((const float4*)(x + (size_t)row0 * 64))[i];
    __syncthreads();
    int r = tid >> 4, c4 = tid & 15;
    float4 acc = make_float4(0.f, 0.f, 0.f, 0.f);
    #pragma unroll 16
    for (int k = 0; k < 64; k++) {
        float xv = sx[r][k];
        float4 w4 = *(const float4*)&sW[k][c4 * 4];
        acc.x += xv * w4.x; acc.y += xv * w4.y; acc.z += xv * w4.z; acc.w += xv * w4.w;
    }
    ((float4*)g_xw)[(size_t)(row0 + r) * 16 + c4] = acc;
}

// ---------------- 10) gather + self-loop + relu + Linear(D,1), fully fused
//   one warp per node; lane holds float2 slice of the 64-dim accumulator ----------------
__global__ void gather_out_kernel(const float* __restrict__ linW, const float* __restrict__ linb,
                                  float* __restrict__ out) {
    int warp = (blockIdx.x * blockDim.x + threadIdx.x) >> 5;
    int lane = threadIdx.x & 31;
    if (warp >= NN) return;
    int start = g_off[warp];
    int end   = start + g_cnt[warp];
    float2 acc = make_float2(0.f, 0.f);
    for (int e = start; e < end; e++) {
        int   src = g_src[e];                       // warp-uniform load (broadcast)
        float nw  = g_wv[e];
        float2 v = ((const float2*)g_xw)[src * 32 + lane];
        acc.x += nw * v.x;
        acc.y += nw * v.y;
    }
    // self-loop: norm = dinv*1*dinv = 1/deg
    float inv = 1.0f / g_deg[warp];
    float2 vs = ((const float2*)g_xw)[warp * 32 + lane];
    acc.x += vs.x * inv;
    acc.y += vs.y * inv;
    acc.x = fmaxf(acc.x, 0.f);
    acc.y = fmaxf(acc.y, 0.f);
    float2 lw = ((const float2*)linW)[lane];
    float dot = acc.x * lw.x + acc.y * lw.y;
    #pragma unroll
    for (int off = 16; off > 0; off >>= 1) dot += __shfl_down_sync(0xffffffffu, dot, off);
    if (lane == 0) out[warp] = dot + linb[0];
}

// ---------------- launch ----------------
extern "C" void kernel_launch(void* const* d_in, const int* in_sizes, int n_in,
                              void* d_out, int out_size) {
    const float* x      = (const float*)d_in[0];
    const int*   ei     = (const int*)d_in[1];     // int32 (JAX x64 disabled)
    const float* ew     = (const float*)d_in[2];
    const float* pool_p = (const float*)d_in[3];
    const float* init_W = (const float*)d_in[4];
    const float* Wih    = (const float*)d_in[5];
    const float* Whh    = (const float*)d_in[6];
    const float* bih    = (const float*)d_in[7];
    const float* bhh    = (const float*)d_in[8];
    const float* linW   = (const float*)d_in[9];
    const float* linb   = (const float*)d_in[10];
    float* out = (float*)d_out;

    zero_kernel<<<(NN + 255) / 256, 256>>>();
    score_kernel<<<(NN + 7) / 8, 256>>>(x, pool_p);
    count_kernel<<<(EE + 255) / 256, 256>>>(ei, ew);
    thresh_kernel<<<1, 256>>>();
    collect_kernel<<<(NN + 255) / 256, 256>>>();
    final_topk_kernel<<<1, 32>>>();
    gru_kernel<<<64, 64>>>(x, pool_p, init_W, Wih, Whh, bih, bhh);
    scan_part_kernel<<<SCAN_NB, SCAN_B>>>();
    scan_top_kernel<<<1, 128>>>();
    scan_add_kernel<<<SCAN_NB, SCAN_B>>>();
    fill_kernel<<<(EE + 255) / 256, 256>>>(ei, ew);
    xw_kernel<<<(NN + 15) / 16, 256>>>(x);
    gather_out_kernel<<<(NN + 7) / 8, 256>>>(linW, linb, out);
}